// round 2
// baseline (speedup 1.0000x reference)
#include <cuda_runtime.h>
#include <cstdint>

#define MARGIN 0.5f
// V*C*(T-1) = 4096*128*127
#define INV_CNT (1.0f / 66584576.0f)

__device__ float    g_partial = 0.0f;
__device__ unsigned g_bcount  = 0;

__device__ __forceinline__ float hinge4(float4 v, float base) {
    return fmaxf(v.x + base, 0.0f) + fmaxf(v.y + base, 0.0f)
         + fmaxf(v.z + base, 0.0f) + fmaxf(v.w + base, 0.0f);
}

__device__ __forceinline__ float pick(float4 v, int t) {
    return (t & 2) ? ((t & 1) ? v.w : v.z)
                   : ((t & 1) ? v.y : v.x);
}

__global__ void __launch_bounds__(256)
margin_loss_kernel(const float* __restrict__ x,
                   const void* __restrict__ tgt,
                   float* __restrict__ out,
                   int rows) {
    const int lane  = threadIdx.x & 31;
    const int wib   = threadIdx.x >> 5;
    const int gwarp = (blockIdx.x * blockDim.x + threadIdx.x) >> 5;
    const int nwarps = (gridDim.x * blockDim.x) >> 5;

    // ---- per-block dtype detection (int64 vs int32 targets) ----
    // If int64 little-endian with values in [0,128), odd 32-bit words are 0.
    // P(false positive for int32) = (1/128)^32 ~ 0. Words hit in L2 after block 0.
    __shared__ int s_is64;
    if (threadIdx.x < 32) {
        int w = ((const int*)tgt)[2 * lane + 1];
        unsigned nz = __ballot_sync(0xffffffffu, w != 0);
        if (lane == 0) s_is64 = (nz == 0u) ? 1 : 0;
    }
    __syncthreads();
    const int is64 = s_is64;

    const float4* __restrict__ x4 = (const float4*)x;
    const long long* __restrict__ t64 = (const long long*)tgt;
    const int* __restrict__ t32 = (const int*)tgt;

    // Each warp owns a contiguous chunk of rows (contiguous 16KB of x).
    const int rpw  = rows / nwarps;            // 524288/16384 = 32
    const int row0 = gwarp * rpw;

    float acc = 0.0f;

    #pragma unroll 1
    for (int r = row0; r < row0 + rpw; r += 4) {
        // front-batch 4 independent 512B row loads -> MLP >= 4
        float4 v0 = __ldg(&x4[(size_t)(r + 0) * 32 + lane]);
        float4 v1 = __ldg(&x4[(size_t)(r + 1) * 32 + lane]);
        float4 v2 = __ldg(&x4[(size_t)(r + 2) * 32 + lane]);
        float4 v3 = __ldg(&x4[(size_t)(r + 3) * 32 + lane]);

        int t0, t1, t2, t3;
        if (is64) {
            t0 = (int)t64[r + 0]; t1 = (int)t64[r + 1];
            t2 = (int)t64[r + 2]; t3 = (int)t64[r + 3];
        } else {
            t0 = t32[r + 0]; t1 = t32[r + 1];
            t2 = t32[r + 2]; t3 = t32[r + 3];
        }

        float p0 = __shfl_sync(0xffffffffu, pick(v0, t0), t0 >> 2);
        float p1 = __shfl_sync(0xffffffffu, pick(v1, t1), t1 >> 2);
        float p2 = __shfl_sync(0xffffffffu, pick(v2, t2), t2 >> 2);
        float p3 = __shfl_sync(0xffffffffu, pick(v3, t3), t3 >> 2);

        acc += hinge4(v0, MARGIN - p0) + hinge4(v1, MARGIN - p1)
             + hinge4(v2, MARGIN - p2) + hinge4(v3, MARGIN - p3);
    }
    // each row's target position contributed exactly MARGIN; remove per row
    if (lane == 0) acc -= MARGIN * (float)rpw;

    // warp reduce
    #pragma unroll
    for (int o = 16; o > 0; o >>= 1)
        acc += __shfl_xor_sync(0xffffffffu, acc, o);

    __shared__ float sdata[8];
    if (lane == 0) sdata[wib] = acc;
    __syncthreads();

    if (wib == 0) {
        float v = (lane < (blockDim.x >> 5)) ? sdata[lane] : 0.0f;
        #pragma unroll
        for (int o = 4; o > 0; o >>= 1)
            v += __shfl_xor_sync(0xffffffffu, v, o);

        if (lane == 0) {
            atomicAdd(&g_partial, v);
            __threadfence();
            unsigned done = atomicInc(&g_bcount, gridDim.x - 1);
            if (done == gridDim.x - 1) {
                // last block: publish result, reset state for next graph replay
                *out = g_partial * INV_CNT;
                g_partial = 0.0f;   // g_bcount already wrapped to 0 by atomicInc
                __threadfence();
            }
        }
    }
}

extern "C" void kernel_launch(void* const* d_in, const int* in_sizes, int n_in,
                              void* d_out, int out_size) {
    const float* x = (const float*)d_in[0];
    const void* tgt = d_in[1];
    float* out = (float*)d_out;

    int rows = in_sizes[1];          // V*C = 524288

    // 2048 blocks x 256 thr = 16384 warps; each warp owns 32 contiguous rows
    margin_loss_kernel<<<2048, 256>>>(x, tgt, out, rows);
}

// round 3
// speedup vs baseline: 1.0990x; 1.0990x over previous
#include <cuda_runtime.h>
#include <cstdint>

#define MARGIN 0.5f

__device__ float    g_partial = 0.0f;
__device__ unsigned g_bcount  = 0;

__device__ __forceinline__ float pick(float4 v, int t) {
    return (t & 2) ? ((t & 1) ? v.w : v.z)
                   : ((t & 1) ? v.y : v.x);
}

__device__ __forceinline__ float hinge4(float4 v, float base) {
    return fmaxf(v.x + base, 0.0f) + fmaxf(v.y + base, 0.0f)
         + fmaxf(v.z + base, 0.0f) + fmaxf(v.w + base, 0.0f);
}

// Consume one 4-row group: broadcast each row's positive, sum hinges.
__device__ __forceinline__ float group4(float4 v0, float4 v1, float4 v2, float4 v3,
                                        int t0, int t1, int t2, int t3) {
    float p0 = __shfl_sync(0xffffffffu, pick(v0, t0), t0 >> 2);
    float p1 = __shfl_sync(0xffffffffu, pick(v1, t1), t1 >> 2);
    float p2 = __shfl_sync(0xffffffffu, pick(v2, t2), t2 >> 2);
    float p3 = __shfl_sync(0xffffffffu, pick(v3, t3), t3 >> 2);
    return hinge4(v0, MARGIN - p0) + hinge4(v1, MARGIN - p1)
         + hinge4(v2, MARGIN - p2) + hinge4(v3, MARGIN - p3);
}

__global__ void __launch_bounds__(256)
margin_loss_kernel(const float* __restrict__ x,
                   const void* __restrict__ tgt,
                   float* __restrict__ out,
                   int rows) {
    const int lane   = threadIdx.x & 31;
    const int wib    = threadIdx.x >> 5;
    const int gwarp  = (blockIdx.x * blockDim.x + threadIdx.x) >> 5;
    const int nwarps = (gridDim.x * blockDim.x) >> 5;

    // ---- dtype detection: int64 little-endian targets in [0,128) have all
    // odd 32-bit words zero. P(false positive for int32) = (1/128)^32 ~ 0.
    __shared__ int s_is64;
    if (threadIdx.x < 32) {
        int w = ((const int*)tgt)[2 * lane + 1];
        unsigned nz = __ballot_sync(0xffffffffu, w != 0);
        if (lane == 0) s_is64 = (nz == 0u) ? 1 : 0;
    }
    __syncthreads();
    const int is64 = s_is64;

    const float4*    __restrict__ x4  = (const float4*)x;
    const long long* __restrict__ t64 = (const long long*)tgt;
    const int*       __restrict__ t32 = (const int*)tgt;

    const int groups = rows >> 2;     // 4-row groups
    float acc = 0.0f;
    int   ngr = 0;

    int g = gwarp;
    if (g < groups) {
        // ---- prologue: prefetch group g ----
        int r = g << 2;
        const float4* pa = &x4[(size_t)r * 32 + lane];
        float4 a0 = __ldcs(pa);
        float4 a1 = __ldcs(pa + 32);
        float4 a2 = __ldcs(pa + 64);
        float4 a3 = __ldcs(pa + 96);
        int ta0, ta1, ta2, ta3;
        if (is64) { ta0 = (int)t64[r]; ta1 = (int)t64[r+1]; ta2 = (int)t64[r+2]; ta3 = (int)t64[r+3]; }
        else      { ta0 = t32[r];      ta1 = t32[r+1];      ta2 = t32[r+2];      ta3 = t32[r+3]; }

        // ---- pipelined mainloop: prefetch next, consume current ----
        #pragma unroll 1
        for (int gn = g + nwarps; gn < groups; gn += nwarps) {
            int rn = gn << 2;
            const float4* pb = &x4[(size_t)rn * 32 + lane];
            float4 b0 = __ldcs(pb);
            float4 b1 = __ldcs(pb + 32);
            float4 b2 = __ldcs(pb + 64);
            float4 b3 = __ldcs(pb + 96);
            int tb0, tb1, tb2, tb3;
            if (is64) { tb0 = (int)t64[rn]; tb1 = (int)t64[rn+1]; tb2 = (int)t64[rn+2]; tb3 = (int)t64[rn+3]; }
            else      { tb0 = t32[rn];      tb1 = t32[rn+1];      tb2 = t32[rn+2];      tb3 = t32[rn+3]; }

            acc += group4(a0, a1, a2, a3, ta0, ta1, ta2, ta3);
            ngr++;

            a0 = b0; a1 = b1; a2 = b2; a3 = b3;
            ta0 = tb0; ta1 = tb1; ta2 = tb2; ta3 = tb3;
        }

        // ---- epilogue: consume last group ----
        acc += group4(a0, a1, a2, a3, ta0, ta1, ta2, ta3);
        ngr++;
    }

    // every processed row's target position contributed exactly MARGIN
    if (lane == 0) acc -= MARGIN * 4.0f * (float)ngr;

    // warp reduce
    #pragma unroll
    for (int o = 16; o > 0; o >>= 1)
        acc += __shfl_xor_sync(0xffffffffu, acc, o);

    __shared__ float sdata[8];
    if (lane == 0) sdata[wib] = acc;
    __syncthreads();

    if (wib == 0) {
        float v = (lane < (blockDim.x >> 5)) ? sdata[lane] : 0.0f;
        #pragma unroll
        for (int o = 4; o > 0; o >>= 1)
            v += __shfl_xor_sync(0xffffffffu, v, o);

        if (lane == 0) {
            atomicAdd(&g_partial, v);
            __threadfence();
            unsigned done = atomicInc(&g_bcount, gridDim.x - 1);
            if (done == gridDim.x - 1) {
                // last block: publish result, reset for next graph replay
                float cnt = (float)rows * 127.0f;   // rows * (T-1), T=128
                *out = g_partial / cnt;
                g_partial = 0.0f;   // g_bcount already wrapped to 0
                __threadfence();
            }
        }
    }
}

extern "C" void kernel_launch(void* const* d_in, const int* in_sizes, int n_in,
                              void* d_out, int out_size) {
    const float* x   = (const float*)d_in[0];
    const void*  tgt = d_in[1];
    float*       out = (float*)d_out;

    int rows = in_sizes[0] >> 7;     // x elements / T(=128) = V*C

    // exact single-wave persistent grid (reg count varies with the pipeline,
    // so query real occupancy rather than hardcode)
    int dev = 0, sms = 148, occ = 8;
    cudaGetDevice(&dev);
    cudaDeviceGetAttribute(&sms, cudaDevAttrMultiProcessorCount, dev);
    cudaOccupancyMaxActiveBlocksPerMultiprocessor(&occ, margin_loss_kernel, 256, 0);
    if (occ < 1) occ = 1;
    int blocks = sms * occ;

    margin_loss_kernel<<<blocks, 256>>>(x, tgt, out, rows);
}